// round 6
// baseline (speedup 1.0000x reference)
#include <cuda_runtime.h>

#define NPTS 6144
#define NITERS 10

// Scratch (static device globals — allocation-free per harness rules)
__device__ unsigned char d_M[(size_t)NPTS * NPTS];   // 37.7 MB u8 matrix, L2-resident
__device__ float d_v0[NPTS];
__device__ float d_v1[NPTS];

__device__ __forceinline__ float fsqrt_approx(float x) {
    float r;
    asm("sqrt.approx.f32 %0, %1;" : "=f"(r) : "f"(x));
    return r;
}

// ---- packed f32x2 helpers (sm_103a) ----
typedef unsigned long long u64t;
__device__ __forceinline__ u64t pk2(float lo, float hi) {
    u64t r; asm("mov.b64 %0, {%1, %2};" : "=l"(r) : "f"(lo), "f"(hi)); return r;
}
__device__ __forceinline__ void upk2(float& lo, float& hi, u64t v) {
    asm("mov.b64 {%0, %1}, %2;" : "=f"(lo), "=f"(hi) : "l"(v));
}
__device__ __forceinline__ u64t add2(u64t a, u64t b) {
    u64t r; asm("add.rn.f32x2 %0, %1, %2;" : "=l"(r) : "l"(a), "l"(b)); return r;
}
__device__ __forceinline__ u64t mul2(u64t a, u64t b) {
    u64t r; asm("mul.rn.f32x2 %0, %1, %2;" : "=l"(r) : "l"(a), "l"(b)); return r;
}
__device__ __forceinline__ u64t fma2(u64t a, u64t b, u64t c) {
    u64t r; asm("fma.rn.f32x2 %0, %1, %2, %3;" : "=l"(r) : "l"(a), "l"(b), "l"(c));
    return r;
}

// Build M in u8 fixed-point: q = round(255 * max(0, 1 - 100*cross^2)),
// cross^2 = a + b - 2*sqrt(a*b), a=|p2_i-p2_j|^2, b=|p3_i-p3_j|^2.
// Packed 2-wide via fma.rn.f32x2; 2^23 magic-add rounding in the last FMA.
// Block (0,0) also initializes d_v0 = ones (saves a launch).
__global__ void __launch_bounds__(256) k_build(const float* __restrict__ p2,
                                               const float* __restrict__ p3) {
    const int tid = threadIdx.x;
    if (blockIdx.x == 0 && blockIdx.y == 0) {
#pragma unroll
        for (int t = 0; t < NPTS / 256; t++) d_v0[tid + 256 * t] = 1.0f;
    }
    const int j0 = (blockIdx.x * 256 + tid) * 8;   // 8 cols
    const int r0 = blockIdx.y * 8;                 // 8 rows

    const float4* p2v = reinterpret_cast<const float4*>(p2);
    const float4* p3v = reinterpret_cast<const float4*>(p3);

    u64t ncx[4], ncy[4], n3x[4], n3y[4], n3z[4];
#pragma unroll
    for (int k = 0; k < 4; k++) {
        float4 a = __ldg(&p2v[j0 / 2 + k]);
        ncx[k] = pk2(-a.x, -a.z);
        ncy[k] = pk2(-a.y, -a.w);
    }
    {
        float q3[24];
#pragma unroll
        for (int k = 0; k < 6; k++) {
            float4 a = __ldg(&p3v[(3 * j0) / 4 + k]);
            q3[4*k] = a.x; q3[4*k+1] = a.y; q3[4*k+2] = a.z; q3[4*k+3] = a.w;
        }
#pragma unroll
        for (int k = 0; k < 4; k++) {
            n3x[k] = pk2(-q3[6*k],   -q3[6*k+3]);
            n3y[k] = pk2(-q3[6*k+1], -q3[6*k+4]);
            n3z[k] = pk2(-q3[6*k+2], -q3[6*k+5]);
        }
    }
    float rx[8], ry[8];
#pragma unroll
    for (int k = 0; k < 4; k++) {
        float4 a = __ldg(&p2v[r0 / 2 + k]);
        rx[2*k] = a.x; ry[2*k] = a.y; rx[2*k+1] = a.z; ry[2*k+1] = a.w;
    }
    float r3[24];
#pragma unroll
    for (int k = 0; k < 6; k++) {
        float4 a = __ldg(&p3v[(3 * r0) / 4 + k]);
        r3[4*k] = a.x; r3[4*k+1] = a.y; r3[4*k+2] = a.z; r3[4*k+3] = a.w;
    }

    const u64t NEG2  = pk2(-2.0f, -2.0f);
    const u64t NEGK  = pk2(-25500.0f, -25500.0f);
    const u64t MAGIC = pk2(8388863.0f, 8388863.0f);

#pragma unroll
    for (int r = 0; r < 8; r++) {
        const u64t sx2 = pk2(rx[r], rx[r]);
        const u64t sy2 = pk2(ry[r], ry[r]);
        const u64t sx3 = pk2(r3[3*r],   r3[3*r]);
        const u64t sy3 = pk2(r3[3*r+1], r3[3*r+1]);
        const u64t sz3 = pk2(r3[3*r+2], r3[3*r+2]);
        unsigned u[8];
#pragma unroll
        for (int p = 0; p < 4; p++) {
            u64t dx = add2(sx2, ncx[p]);
            u64t dy = add2(sy2, ncy[p]);
            u64t a  = fma2(dx, dx, mul2(dy, dy));
            u64t d0 = add2(sx3, n3x[p]);
            u64t d1 = add2(sy3, n3y[p]);
            u64t d2 = add2(sz3, n3z[p]);
            u64t b  = fma2(d2, d2, fma2(d1, d1, mul2(d0, d0)));
            u64t ab = mul2(a, b);
            u64t apb = add2(a, b);
            float ab0, ab1;
            upk2(ab0, ab1, ab);
            u64t s  = pk2(fsqrt_approx(ab0), fsqrt_approx(ab1));
            u64t cr = fma2(NEG2, s, apb);       // (sqrt a - sqrt b)^2
            u64t t  = fma2(NEGK, cr, MAGIC);    // 2^23 + 255 - 25500*cr
            float t0, t1;
            upk2(t0, t1, t);
            t0 = fminf(fmaxf(t0, 8388608.0f), 8388863.0f);
            t1 = fminf(fmaxf(t1, 8388608.0f), 8388863.0f);
            u[2*p]   = __float_as_uint(t0);     // byte = low 8 mantissa bits
            u[2*p+1] = __float_as_uint(t1);
        }
        unsigned w0 = __byte_perm(__byte_perm(u[0], u[1], 0x0040),
                                  __byte_perm(u[2], u[3], 0x0040), 0x5410);
        unsigned w1 = __byte_perm(__byte_perm(u[4], u[5], 0x0040),
                                  __byte_perm(u[6], u[7], 0x0040), 0x5410);
        *reinterpret_cast<uint2*>(&d_M[(size_t)(r0 + r) * NPTS + j0]) =
            make_uint2(w0, w1);
    }
}

// One power-iteration step via integer dp4a.
// 8 warps x 2 rows = 16 rows/block, grid 384. x staged once per block as
// u16 lo/hi u8 planes. M streamed with __ldcg (L2-only; x stays hot in L1).
// Mainloop: 2 batches of 12 front-batched LDG.128 (MLP=12/warp) to cover
// L2 latency; __launch_bounds__(256,3) gives ~80 regs without losing
// co-residency (3 blocks/SM >= 2.6 needed for a single wave).
__global__ void __launch_bounds__(256, 3) k_gemv(int k) {
    const float* __restrict__ x = (k & 1) ? d_v1 : d_v0;
    float* __restrict__       y = (k & 1) ? d_v0 : d_v1;

    __shared__ unsigned sxlo[NPTS / 4];   // 1536 words, lo bytes of xq
    __shared__ unsigned sxhi[NPTS / 4];   // hi bytes
    __shared__ float red[8];

    const int tid = threadIdx.x;
    const float4* xv = reinterpret_cast<const float4*>(x);

    float4 v[6];
    float ss = 0.0f;
#pragma unroll
    for (int t = 0; t < 6; t++) {
        v[t] = xv[tid + 256 * t];
        ss = fmaf(v[t].x, v[t].x, fmaf(v[t].y, v[t].y,
             fmaf(v[t].z, v[t].z, fmaf(v[t].w, v[t].w, ss))));
    }
#pragma unroll
    for (int o = 16; o; o >>= 1) ss += __shfl_xor_sync(0xffffffffu, ss, o);
    const int warp = tid >> 5, lane = tid & 31;
    if (lane == 0) red[warp] = ss;
    __syncthreads();
    ss = 0.0f;
#pragma unroll
    for (int w = 0; w < 8; w++) ss += red[w];

    const float inv = (k == 0) ? 1.0f : (1.0f / (sqrtf(ss) + 1e-6f));
    const float qs  = 65535.0f * inv;

#pragma unroll
    for (int t = 0; t < 6; t++) {
        unsigned q0 = __float2uint_rn(v[t].x * qs);
        unsigned q1 = __float2uint_rn(v[t].y * qs);
        unsigned q2 = __float2uint_rn(v[t].z * qs);
        unsigned q3 = __float2uint_rn(v[t].w * qs);
        const int f = tid + 256 * t;
        sxlo[f] = (q0 & 255u) | ((q1 & 255u) << 8) |
                  ((q2 & 255u) << 16) | ((q3 & 255u) << 24);
        sxhi[f] = (q0 >> 8) | ((q1 >> 8) << 8) |
                  ((q2 >> 8) << 16) | ((q3 >> 8) << 24);
    }
    __syncthreads();

    const int r0 = blockIdx.x * 16 + warp * 2;
    const uint4* M4  = reinterpret_cast<const uint4*>(d_M);
    const uint4* sl4 = reinterpret_cast<const uint4*>(sxlo);
    const uint4* sh4 = reinterpret_cast<const uint4*>(sxhi);
    const size_t rb = (size_t)r0 * (NPTS / 16);

    unsigned lo0 = 0, hi0 = 0, lo1 = 0, hi1 = 0;
#pragma unroll
    for (int h = 0; h < 2; h++) {
        // Front-batch 12 LDG.128 (6 chunks x 2 rows) — MLP=12 in flight.
        uint4 g0[6], g1[6];
#pragma unroll
        for (int i = 0; i < 6; i++) {
            const int c = (h * 6 + i) * 32 + lane;
            g0[i] = __ldcg(&M4[rb + c]);
            g1[i] = __ldcg(&M4[rb + (NPTS / 16) + c]);
        }
#pragma unroll
        for (int i = 0; i < 6; i++) {
            const int c = (h * 6 + i) * 32 + lane;
            uint4 xl = sl4[c];
            uint4 xh = sh4[c];
            uint4 m0 = g0[i];
            uint4 m1 = g1[i];
            lo0 = __dp4a(m0.x, xl.x, lo0); hi0 = __dp4a(m0.x, xh.x, hi0);
            lo0 = __dp4a(m0.y, xl.y, lo0); hi0 = __dp4a(m0.y, xh.y, hi0);
            lo0 = __dp4a(m0.z, xl.z, lo0); hi0 = __dp4a(m0.z, xh.z, hi0);
            lo0 = __dp4a(m0.w, xl.w, lo0); hi0 = __dp4a(m0.w, xh.w, hi0);
            lo1 = __dp4a(m1.x, xl.x, lo1); hi1 = __dp4a(m1.x, xh.x, hi1);
            lo1 = __dp4a(m1.y, xl.y, lo1); hi1 = __dp4a(m1.y, xh.y, hi1);
            lo1 = __dp4a(m1.z, xl.z, lo1); hi1 = __dp4a(m1.z, xh.z, hi1);
            lo1 = __dp4a(m1.w, xl.w, lo1); hi1 = __dp4a(m1.w, xh.w, hi1);
        }
    }
#pragma unroll
    for (int o = 16; o; o >>= 1) {
        lo0 += __shfl_xor_sync(0xffffffffu, lo0, o);
        hi0 += __shfl_xor_sync(0xffffffffu, hi0, o);
        lo1 += __shfl_xor_sync(0xffffffffu, lo1, o);
        hi1 += __shfl_xor_sync(0xffffffffu, hi1, o);
    }
    if (lane == 0) {
        const float outsc = 1.0f / (255.0f * 65535.0f);
        y[r0    ] = ((float)lo0 + 256.0f * (float)hi0) * outsc;
        y[r0 + 1] = ((float)lo1 + 256.0f * (float)hi1) * outsc;
    }
}

// Final normalization into d_out (last raw result in d_v0 after 10 iters).
__global__ void __launch_bounds__(256) k_final(float* __restrict__ out) {
    __shared__ float red[8];
    const int tid = threadIdx.x;
    float ss = 0.0f;
#pragma unroll
    for (int t = 0; t < 24; t++) {
        float v = d_v0[tid + 256 * t];
        ss = fmaf(v, v, ss);
    }
#pragma unroll
    for (int o = 16; o; o >>= 1) ss += __shfl_xor_sync(0xffffffffu, ss, o);
    if ((tid & 31) == 0) red[tid >> 5] = ss;
    __syncthreads();
    ss = 0.0f;
#pragma unroll
    for (int w = 0; w < 8; w++) ss += red[w];
    const float inv = 1.0f / (sqrtf(ss) + 1e-6f);
    const int i = blockIdx.x * 256 + tid;
    out[i] = d_v0[i] * inv;
}

extern "C" void kernel_launch(void* const* d_in, const int* in_sizes, int n_in,
                              void* d_out, int out_size) {
    const float* p2 = (const float*)d_in[0];  // ipts2d (N,2) fp32
    const float* p3 = (const float*)d_in[1];  // ipts3d (N,3) fp32

    dim3 bgrid(3, NPTS / 8);                  // 8x8 tile per thread
    k_build<<<bgrid, 256>>>(p2, p3);
    for (int k = 0; k < NITERS; k++)
        k_gemv<<<NPTS / 16, 256>>>(k);        // 384 blocks, 16 rows each
    k_final<<<NPTS / 256, 256>>>((float*)d_out);
}

// round 7
// speedup vs baseline: 1.0092x; 1.0092x over previous
#include <cuda_runtime.h>

#define NPTS 6144
#define NITERS 10
#define GRID 384          // persistent gemv grid; all CTAs co-resident

// Scratch (static device globals — allocation-free per harness rules)
__device__ unsigned char d_M[(size_t)NPTS * NPTS];   // 37.7 MB u8 matrix
__device__ float d_v0[NPTS];
__device__ float d_v1[NPTS];
__device__ unsigned g_cnt;   // monotone grid-barrier ticket (survives replays)

__device__ __forceinline__ float fsqrt_approx(float x) {
    float r;
    asm("sqrt.approx.f32 %0, %1;" : "=f"(r) : "f"(x));
    return r;
}

// ---- packed f32x2 helpers (sm_103a) ----
typedef unsigned long long u64t;
__device__ __forceinline__ u64t pk2(float lo, float hi) {
    u64t r; asm("mov.b64 %0, {%1, %2};" : "=l"(r) : "f"(lo), "f"(hi)); return r;
}
__device__ __forceinline__ void upk2(float& lo, float& hi, u64t v) {
    asm("mov.b64 {%0, %1}, %2;" : "=f"(lo), "=f"(hi) : "l"(v));
}
__device__ __forceinline__ u64t add2(u64t a, u64t b) {
    u64t r; asm("add.rn.f32x2 %0, %1, %2;" : "=l"(r) : "l"(a), "l"(b)); return r;
}
__device__ __forceinline__ u64t mul2(u64t a, u64t b) {
    u64t r; asm("mul.rn.f32x2 %0, %1, %2;" : "=l"(r) : "l"(a), "l"(b)); return r;
}
__device__ __forceinline__ u64t fma2(u64t a, u64t b, u64t c) {
    u64t r; asm("fma.rn.f32x2 %0, %1, %2, %3;" : "=l"(r) : "l"(a), "l"(b), "l"(c));
    return r;
}

// Build M in u8 fixed-point: q = round(255 * max(0, 1 - 100*cross^2)),
// cross^2 = a + b - 2*sqrt(a*b), a=|p2_i-p2_j|^2, b=|p3_i-p3_j|^2.
// Packed 2-wide via fma.rn.f32x2; 2^23 magic-add rounding in the last FMA.
// Block (0,0) also initializes d_v0 = ones.
__global__ void __launch_bounds__(256) k_build(const float* __restrict__ p2,
                                               const float* __restrict__ p3) {
    const int tid = threadIdx.x;
    if (blockIdx.x == 0 && blockIdx.y == 0) {
#pragma unroll
        for (int t = 0; t < NPTS / 256; t++) d_v0[tid + 256 * t] = 1.0f;
    }
    const int j0 = (blockIdx.x * 256 + tid) * 8;   // 8 cols
    const int r0 = blockIdx.y * 8;                 // 8 rows

    const float4* p2v = reinterpret_cast<const float4*>(p2);
    const float4* p3v = reinterpret_cast<const float4*>(p3);

    u64t ncx[4], ncy[4], n3x[4], n3y[4], n3z[4];
#pragma unroll
    for (int k = 0; k < 4; k++) {
        float4 a = __ldg(&p2v[j0 / 2 + k]);
        ncx[k] = pk2(-a.x, -a.z);
        ncy[k] = pk2(-a.y, -a.w);
    }
    {
        float q3[24];
#pragma unroll
        for (int k = 0; k < 6; k++) {
            float4 a = __ldg(&p3v[(3 * j0) / 4 + k]);
            q3[4*k] = a.x; q3[4*k+1] = a.y; q3[4*k+2] = a.z; q3[4*k+3] = a.w;
        }
#pragma unroll
        for (int k = 0; k < 4; k++) {
            n3x[k] = pk2(-q3[6*k],   -q3[6*k+3]);
            n3y[k] = pk2(-q3[6*k+1], -q3[6*k+4]);
            n3z[k] = pk2(-q3[6*k+2], -q3[6*k+5]);
        }
    }
    float rx[8], ry[8];
#pragma unroll
    for (int k = 0; k < 4; k++) {
        float4 a = __ldg(&p2v[r0 / 2 + k]);
        rx[2*k] = a.x; ry[2*k] = a.y; rx[2*k+1] = a.z; ry[2*k+1] = a.w;
    }
    float r3[24];
#pragma unroll
    for (int k = 0; k < 6; k++) {
        float4 a = __ldg(&p3v[(3 * r0) / 4 + k]);
        r3[4*k] = a.x; r3[4*k+1] = a.y; r3[4*k+2] = a.z; r3[4*k+3] = a.w;
    }

    const u64t NEG2  = pk2(-2.0f, -2.0f);
    const u64t NEGK  = pk2(-25500.0f, -25500.0f);
    const u64t MAGIC = pk2(8388863.0f, 8388863.0f);

#pragma unroll
    for (int r = 0; r < 8; r++) {
        const u64t sx2 = pk2(rx[r], rx[r]);
        const u64t sy2 = pk2(ry[r], ry[r]);
        const u64t sx3 = pk2(r3[3*r],   r3[3*r]);
        const u64t sy3 = pk2(r3[3*r+1], r3[3*r+1]);
        const u64t sz3 = pk2(r3[3*r+2], r3[3*r+2]);
        unsigned u[8];
#pragma unroll
        for (int p = 0; p < 4; p++) {
            u64t dx = add2(sx2, ncx[p]);
            u64t dy = add2(sy2, ncy[p]);
            u64t a  = fma2(dx, dx, mul2(dy, dy));
            u64t d0 = add2(sx3, n3x[p]);
            u64t d1 = add2(sy3, n3y[p]);
            u64t d2 = add2(sz3, n3z[p]);
            u64t b  = fma2(d2, d2, fma2(d1, d1, mul2(d0, d0)));
            u64t ab = mul2(a, b);
            u64t apb = add2(a, b);
            float ab0, ab1;
            upk2(ab0, ab1, ab);
            u64t s  = pk2(fsqrt_approx(ab0), fsqrt_approx(ab1));
            u64t cr = fma2(NEG2, s, apb);       // (sqrt a - sqrt b)^2
            u64t t  = fma2(NEGK, cr, MAGIC);    // 2^23 + 255 - 25500*cr
            float t0, t1;
            upk2(t0, t1, t);
            t0 = fminf(fmaxf(t0, 8388608.0f), 8388863.0f);
            t1 = fminf(fmaxf(t1, 8388608.0f), 8388863.0f);
            u[2*p]   = __float_as_uint(t0);     // byte = low 8 mantissa bits
            u[2*p+1] = __float_as_uint(t1);
        }
        unsigned w0 = __byte_perm(__byte_perm(u[0], u[1], 0x0040),
                                  __byte_perm(u[2], u[3], 0x0040), 0x5410);
        unsigned w1 = __byte_perm(__byte_perm(u[4], u[5], 0x0040),
                                  __byte_perm(u[6], u[7], 0x0040), 0x5410);
        *reinterpret_cast<uint2*>(&d_M[(size_t)(r0 + r) * NPTS + j0]) =
            make_uint2(w0, w1);
    }
}

// Software grid barrier. Monotone ticket counter: works across graph replays
// without reset (counter is always a multiple of GRID at barrier boundaries).
__device__ __forceinline__ void grid_barrier() {
    __syncthreads();
    if (threadIdx.x == 0) {
        __threadfence();
        unsigned old = atomicAdd(&g_cnt, 1u);
        unsigned target = old - (old % GRID) + GRID;
        while (*((volatile unsigned*)&g_cnt) < target) __nanosleep(32);
    }
    __syncthreads();
}

// Persistent kernel: all 10 power iterations + final normalization.
// Block b owns rows [16b, 16b+16) for the whole launch, so its M rows stay
// hot in L1 across iterations (L1 persists within a launch) -> M via __ldg.
// x/y vectors are re-read each iteration and MUST bypass L1 (__ldcg) to
// avoid stale lines from 2 iterations ago.
__global__ void __launch_bounds__(256) k_iter(float* __restrict__ out) {
    __shared__ unsigned sxlo[NPTS / 4];   // lo bytes of xq (u16 planes)
    __shared__ unsigned sxhi[NPTS / 4];
    __shared__ float red[8];

    const int tid = threadIdx.x;
    const int warp = tid >> 5, lane = tid & 31;
    const int r0 = blockIdx.x * 16 + warp * 2;
    const uint4* M4  = reinterpret_cast<const uint4*>(d_M);
    const uint4* sl4 = reinterpret_cast<const uint4*>(sxlo);
    const uint4* sh4 = reinterpret_cast<const uint4*>(sxhi);
    const size_t rb = (size_t)r0 * (NPTS / 16);

    for (int k = 0; k < NITERS; k++) {
        const float* __restrict__ x = (k & 1) ? d_v1 : d_v0;
        float* __restrict__       y = (k & 1) ? d_v0 : d_v1;
        const float4* xv = reinterpret_cast<const float4*>(x);

        // Stage + norm + quantize (x via L2 only — L1 may hold stale lines)
        float4 v[6];
        float ss = 0.0f;
#pragma unroll
        for (int t = 0; t < 6; t++) {
            v[t] = __ldcg(&xv[tid + 256 * t]);
            ss = fmaf(v[t].x, v[t].x, fmaf(v[t].y, v[t].y,
                 fmaf(v[t].z, v[t].z, fmaf(v[t].w, v[t].w, ss))));
        }
#pragma unroll
        for (int o = 16; o; o >>= 1) ss += __shfl_xor_sync(0xffffffffu, ss, o);
        if (lane == 0) red[warp] = ss;
        __syncthreads();
        ss = 0.0f;
#pragma unroll
        for (int w = 0; w < 8; w++) ss += red[w];

        const float inv = (k == 0) ? 1.0f : (1.0f / (sqrtf(ss) + 1e-6f));
        const float qs  = 65535.0f * inv;

#pragma unroll
        for (int t = 0; t < 6; t++) {
            unsigned q0 = __float2uint_rn(v[t].x * qs);
            unsigned q1 = __float2uint_rn(v[t].y * qs);
            unsigned q2 = __float2uint_rn(v[t].z * qs);
            unsigned q3 = __float2uint_rn(v[t].w * qs);
            const int f = tid + 256 * t;
            sxlo[f] = (q0 & 255u) | ((q1 & 255u) << 8) |
                      ((q2 & 255u) << 16) | ((q3 & 255u) << 24);
            sxhi[f] = (q0 >> 8) | ((q1 >> 8) << 8) |
                      ((q2 >> 8) << 16) | ((q3 >> 8) << 24);
        }
        __syncthreads();

        unsigned lo0 = 0, hi0 = 0, lo1 = 0, hi1 = 0;
#pragma unroll
        for (int it = 0; it < 12; it++) {
            const int c = it * 32 + lane;     // 16-column chunk id
            uint4 xl = sl4[c];
            uint4 xh = sh4[c];
            uint4 m0 = __ldg(&M4[rb + c]);                 // L1-cached
            uint4 m1 = __ldg(&M4[rb + (NPTS / 16) + c]);
            lo0 = __dp4a(m0.x, xl.x, lo0); hi0 = __dp4a(m0.x, xh.x, hi0);
            lo0 = __dp4a(m0.y, xl.y, lo0); hi0 = __dp4a(m0.y, xh.y, hi0);
            lo0 = __dp4a(m0.z, xl.z, lo0); hi0 = __dp4a(m0.z, xh.z, hi0);
            lo0 = __dp4a(m0.w, xl.w, lo0); hi0 = __dp4a(m0.w, xh.w, hi0);
            lo1 = __dp4a(m1.x, xl.x, lo1); hi1 = __dp4a(m1.x, xh.x, hi1);
            lo1 = __dp4a(m1.y, xl.y, lo1); hi1 = __dp4a(m1.y, xh.y, hi1);
            lo1 = __dp4a(m1.z, xl.z, lo1); hi1 = __dp4a(m1.z, xh.z, hi1);
            lo1 = __dp4a(m1.w, xl.w, lo1); hi1 = __dp4a(m1.w, xh.w, hi1);
        }
#pragma unroll
        for (int o = 16; o; o >>= 1) {
            lo0 += __shfl_xor_sync(0xffffffffu, lo0, o);
            hi0 += __shfl_xor_sync(0xffffffffu, hi0, o);
            lo1 += __shfl_xor_sync(0xffffffffu, lo1, o);
            hi1 += __shfl_xor_sync(0xffffffffu, hi1, o);
        }
        if (lane == 0) {
            const float outsc = 1.0f / (255.0f * 65535.0f);
            y[r0    ] = ((float)lo0 + 256.0f * (float)hi0) * outsc;
            y[r0 + 1] = ((float)lo1 + 256.0f * (float)hi1) * outsc;
        }
        grid_barrier();   // includes __threadfence before arrival
    }

    // Final normalization. Last result is in d_v0 (k=9 wrote y=d_v0).
    {
        float ss = 0.0f;
        const float4* xv = reinterpret_cast<const float4*>(d_v0);
#pragma unroll
        for (int t = 0; t < 6; t++) {
            float4 v = __ldcg(&xv[tid + 256 * t]);
            ss = fmaf(v.x, v.x, fmaf(v.y, v.y,
                 fmaf(v.z, v.z, fmaf(v.w, v.w, ss))));
        }
#pragma unroll
        for (int o = 16; o; o >>= 1) ss += __shfl_xor_sync(0xffffffffu, ss, o);
        if (lane == 0) red[warp] = ss;
        __syncthreads();
        ss = 0.0f;
#pragma unroll
        for (int w = 0; w < 8; w++) ss += red[w];
        const float inv = 1.0f / (sqrtf(ss) + 1e-6f);
        if (tid < 16) {
            const int i = blockIdx.x * 16 + tid;
            out[i] = __ldcg(&d_v0[i]) * inv;
        }
    }
}

extern "C" void kernel_launch(void* const* d_in, const int* in_sizes, int n_in,
                              void* d_out, int out_size) {
    const float* p2 = (const float*)d_in[0];  // ipts2d (N,2) fp32
    const float* p3 = (const float*)d_in[1];  // ipts3d (N,3) fp32

    dim3 bgrid(3, NPTS / 8);                  // 8x8 tile per thread
    k_build<<<bgrid, 256>>>(p2, p3);
    k_iter<<<GRID, 256>>>((float*)d_out);     // persistent: 10 iters + final
}

// round 8
// speedup vs baseline: 1.0754x; 1.0655x over previous
#include <cuda_runtime.h>

#define NPTS 6144
#define NITERS 10
#define GRID 128          // persistent grid: 1 CTA/SM, perfectly balanced wave

// Scratch (static device globals — allocation-free per harness rules)
__device__ unsigned char d_M[(size_t)NPTS * NPTS];   // 37.7 MB u8 matrix
__device__ float d_v0[NPTS];
__device__ float d_v1[NPTS];
__device__ unsigned g_cnt;   // monotone grid-barrier ticket (survives replays)

__device__ __forceinline__ float fsqrt_approx(float x) {
    float r;
    asm("sqrt.approx.f32 %0, %1;" : "=f"(r) : "f"(x));
    return r;
}

// ---- packed f32x2 helpers (sm_103a) ----
typedef unsigned long long u64t;
__device__ __forceinline__ u64t pk2(float lo, float hi) {
    u64t r; asm("mov.b64 %0, {%1, %2};" : "=l"(r) : "f"(lo), "f"(hi)); return r;
}
__device__ __forceinline__ void upk2(float& lo, float& hi, u64t v) {
    asm("mov.b64 {%0, %1}, %2;" : "=f"(lo), "=f"(hi) : "l"(v));
}
__device__ __forceinline__ u64t add2(u64t a, u64t b) {
    u64t r; asm("add.rn.f32x2 %0, %1, %2;" : "=l"(r) : "l"(a), "l"(b)); return r;
}
__device__ __forceinline__ u64t mul2(u64t a, u64t b) {
    u64t r; asm("mul.rn.f32x2 %0, %1, %2;" : "=l"(r) : "l"(a), "l"(b)); return r;
}
__device__ __forceinline__ u64t fma2(u64t a, u64t b, u64t c) {
    u64t r; asm("fma.rn.f32x2 %0, %1, %2, %3;" : "=l"(r) : "l"(a), "l"(b), "l"(c));
    return r;
}

// Build M in u8 fixed-point: q = round(255 * max(0, 1 - 100*cross^2)),
// cross^2 = a + b - 2*sqrt(a*b), a=|p2_i-p2_j|^2, b=|p3_i-p3_j|^2.
// Packed 2-wide via fma.rn.f32x2; 2^23 magic-add rounding in the last FMA.
// Block (0,0) also initializes d_v0 = ones.
__global__ void __launch_bounds__(256) k_build(const float* __restrict__ p2,
                                               const float* __restrict__ p3) {
    const int tid = threadIdx.x;
    if (blockIdx.x == 0 && blockIdx.y == 0) {
#pragma unroll
        for (int t = 0; t < NPTS / 256; t++) d_v0[tid + 256 * t] = 1.0f;
    }
    const int j0 = (blockIdx.x * 256 + tid) * 8;   // 8 cols
    const int r0 = blockIdx.y * 8;                 // 8 rows

    const float4* p2v = reinterpret_cast<const float4*>(p2);
    const float4* p3v = reinterpret_cast<const float4*>(p3);

    u64t ncx[4], ncy[4], n3x[4], n3y[4], n3z[4];
#pragma unroll
    for (int k = 0; k < 4; k++) {
        float4 a = __ldg(&p2v[j0 / 2 + k]);
        ncx[k] = pk2(-a.x, -a.z);
        ncy[k] = pk2(-a.y, -a.w);
    }
    {
        float q3[24];
#pragma unroll
        for (int k = 0; k < 6; k++) {
            float4 a = __ldg(&p3v[(3 * j0) / 4 + k]);
            q3[4*k] = a.x; q3[4*k+1] = a.y; q3[4*k+2] = a.z; q3[4*k+3] = a.w;
        }
#pragma unroll
        for (int k = 0; k < 4; k++) {
            n3x[k] = pk2(-q3[6*k],   -q3[6*k+3]);
            n3y[k] = pk2(-q3[6*k+1], -q3[6*k+4]);
            n3z[k] = pk2(-q3[6*k+2], -q3[6*k+5]);
        }
    }
    float rx[8], ry[8];
#pragma unroll
    for (int k = 0; k < 4; k++) {
        float4 a = __ldg(&p2v[r0 / 2 + k]);
        rx[2*k] = a.x; ry[2*k] = a.y; rx[2*k+1] = a.z; ry[2*k+1] = a.w;
    }
    float r3[24];
#pragma unroll
    for (int k = 0; k < 6; k++) {
        float4 a = __ldg(&p3v[(3 * r0) / 4 + k]);
        r3[4*k] = a.x; r3[4*k+1] = a.y; r3[4*k+2] = a.z; r3[4*k+3] = a.w;
    }

    const u64t NEG2  = pk2(-2.0f, -2.0f);
    const u64t NEGK  = pk2(-25500.0f, -25500.0f);
    const u64t MAGIC = pk2(8388863.0f, 8388863.0f);

#pragma unroll
    for (int r = 0; r < 8; r++) {
        const u64t sx2 = pk2(rx[r], rx[r]);
        const u64t sy2 = pk2(ry[r], ry[r]);
        const u64t sx3 = pk2(r3[3*r],   r3[3*r]);
        const u64t sy3 = pk2(r3[3*r+1], r3[3*r+1]);
        const u64t sz3 = pk2(r3[3*r+2], r3[3*r+2]);
        unsigned u[8];
#pragma unroll
        for (int p = 0; p < 4; p++) {
            u64t dx = add2(sx2, ncx[p]);
            u64t dy = add2(sy2, ncy[p]);
            u64t a  = fma2(dx, dx, mul2(dy, dy));
            u64t d0 = add2(sx3, n3x[p]);
            u64t d1 = add2(sy3, n3y[p]);
            u64t d2 = add2(sz3, n3z[p]);
            u64t b  = fma2(d2, d2, fma2(d1, d1, mul2(d0, d0)));
            u64t ab = mul2(a, b);
            u64t apb = add2(a, b);
            float ab0, ab1;
            upk2(ab0, ab1, ab);
            u64t s  = pk2(fsqrt_approx(ab0), fsqrt_approx(ab1));
            u64t cr = fma2(NEG2, s, apb);       // (sqrt a - sqrt b)^2
            u64t t  = fma2(NEGK, cr, MAGIC);    // 2^23 + 255 - 25500*cr
            float t0, t1;
            upk2(t0, t1, t);
            t0 = fminf(fmaxf(t0, 8388608.0f), 8388863.0f);
            t1 = fminf(fmaxf(t1, 8388608.0f), 8388863.0f);
            u[2*p]   = __float_as_uint(t0);     // byte = low 8 mantissa bits
            u[2*p+1] = __float_as_uint(t1);
        }
        unsigned w0 = __byte_perm(__byte_perm(u[0], u[1], 0x0040),
                                  __byte_perm(u[2], u[3], 0x0040), 0x5410);
        unsigned w1 = __byte_perm(__byte_perm(u[4], u[5], 0x0040),
                                  __byte_perm(u[6], u[7], 0x0040), 0x5410);
        *reinterpret_cast<uint2*>(&d_M[(size_t)(r0 + r) * NPTS + j0]) =
            make_uint2(w0, w1);
    }
}

// Software grid barrier. Monotone ticket counter: works across graph replays
// without reset (counter is always a multiple of GRID at barrier boundaries).
__device__ __forceinline__ void grid_barrier() {
    __syncthreads();
    if (threadIdx.x == 0) {
        __threadfence();
        unsigned old = atomicAdd(&g_cnt, 1u);
        unsigned target = old - (old % GRID) + GRID;
        while (*((volatile unsigned*)&g_cnt) < target) __nanosleep(32);
    }
    __syncthreads();
}

// Persistent kernel: 10 power iterations + final normalization.
// grid=128, block=512: one CTA per SM, 16 warps x 3 rows = 48 rows/CTA.
// The CTA's 48 M-rows (295KB) mostly fit its SM's L1 -> __ldg for M; the
// x/y vectors must bypass stale L1 (__ldcg). Exact integer dp4a math.
__global__ void __launch_bounds__(512) k_iter(float* __restrict__ out) {
    __shared__ unsigned sxlo[NPTS / 4];   // lo bytes of xq (u16 planes)
    __shared__ unsigned sxhi[NPTS / 4];
    __shared__ float red[16];

    const int tid = threadIdx.x;
    const int warp = tid >> 5, lane = tid & 31;
    const int r0 = blockIdx.x * 48 + warp * 3;
    const uint4* M4  = reinterpret_cast<const uint4*>(d_M);
    const uint4* sl4 = reinterpret_cast<const uint4*>(sxlo);
    const uint4* sh4 = reinterpret_cast<const uint4*>(sxhi);
    const size_t rb = (size_t)r0 * (NPTS / 16);

    for (int k = 0; k < NITERS; k++) {
        const float* __restrict__ x = (k & 1) ? d_v1 : d_v0;
        float* __restrict__       y = (k & 1) ? d_v0 : d_v1;
        const float4* xv = reinterpret_cast<const float4*>(x);

        // Stage + norm + quantize (x via L2 only — L1 may hold stale lines)
        float4 v[3];
        float ss = 0.0f;
#pragma unroll
        for (int t = 0; t < 3; t++) {
            v[t] = __ldcg(&xv[tid + 512 * t]);
            ss = fmaf(v[t].x, v[t].x, fmaf(v[t].y, v[t].y,
                 fmaf(v[t].z, v[t].z, fmaf(v[t].w, v[t].w, ss))));
        }
#pragma unroll
        for (int o = 16; o; o >>= 1) ss += __shfl_xor_sync(0xffffffffu, ss, o);
        if (lane == 0) red[warp] = ss;
        __syncthreads();
        ss = 0.0f;
#pragma unroll
        for (int w = 0; w < 16; w++) ss += red[w];

        const float inv = (k == 0) ? 1.0f : (1.0f / (sqrtf(ss) + 1e-6f));
        const float qs  = 65535.0f * inv;

#pragma unroll
        for (int t = 0; t < 3; t++) {
            unsigned q0 = __float2uint_rn(v[t].x * qs);
            unsigned q1 = __float2uint_rn(v[t].y * qs);
            unsigned q2 = __float2uint_rn(v[t].z * qs);
            unsigned q3 = __float2uint_rn(v[t].w * qs);
            const int f = tid + 512 * t;
            sxlo[f] = (q0 & 255u) | ((q1 & 255u) << 8) |
                      ((q2 & 255u) << 16) | ((q3 & 255u) << 24);
            sxhi[f] = (q0 >> 8) | ((q1 >> 8) << 8) |
                      ((q2 >> 8) << 16) | ((q3 >> 8) << 24);
        }
        __syncthreads();

        unsigned lo0 = 0, hi0 = 0, lo1 = 0, hi1 = 0, lo2 = 0, hi2 = 0;
#pragma unroll
        for (int it = 0; it < 12; it++) {
            const int c = it * 32 + lane;     // 16-column chunk id
            uint4 xl = sl4[c];
            uint4 xh = sh4[c];
            uint4 m0 = __ldg(&M4[rb + c]);                    // L1-cached
            uint4 m1 = __ldg(&M4[rb + 1 * (NPTS / 16) + c]);
            uint4 m2 = __ldg(&M4[rb + 2 * (NPTS / 16) + c]);
            lo0 = __dp4a(m0.x, xl.x, lo0); hi0 = __dp4a(m0.x, xh.x, hi0);
            lo0 = __dp4a(m0.y, xl.y, lo0); hi0 = __dp4a(m0.y, xh.y, hi0);
            lo0 = __dp4a(m0.z, xl.z, lo0); hi0 = __dp4a(m0.z, xh.z, hi0);
            lo0 = __dp4a(m0.w, xl.w, lo0); hi0 = __dp4a(m0.w, xh.w, hi0);
            lo1 = __dp4a(m1.x, xl.x, lo1); hi1 = __dp4a(m1.x, xh.x, hi1);
            lo1 = __dp4a(m1.y, xl.y, lo1); hi1 = __dp4a(m1.y, xh.y, hi1);
            lo1 = __dp4a(m1.z, xl.z, lo1); hi1 = __dp4a(m1.z, xh.z, hi1);
            lo1 = __dp4a(m1.w, xl.w, lo1); hi1 = __dp4a(m1.w, xh.w, hi1);
            lo2 = __dp4a(m2.x, xl.x, lo2); hi2 = __dp4a(m2.x, xh.x, hi2);
            lo2 = __dp4a(m2.y, xl.y, lo2); hi2 = __dp4a(m2.y, xh.y, hi2);
            lo2 = __dp4a(m2.z, xl.z, lo2); hi2 = __dp4a(m2.z, xh.z, hi2);
            lo2 = __dp4a(m2.w, xl.w, lo2); hi2 = __dp4a(m2.w, xh.w, hi2);
        }
#pragma unroll
        for (int o = 16; o; o >>= 1) {
            lo0 += __shfl_xor_sync(0xffffffffu, lo0, o);
            hi0 += __shfl_xor_sync(0xffffffffu, hi0, o);
            lo1 += __shfl_xor_sync(0xffffffffu, lo1, o);
            hi1 += __shfl_xor_sync(0xffffffffu, hi1, o);
            lo2 += __shfl_xor_sync(0xffffffffu, lo2, o);
            hi2 += __shfl_xor_sync(0xffffffffu, hi2, o);
        }
        if (lane == 0) {
            const float outsc = 1.0f / (255.0f * 65535.0f);
            y[r0    ] = ((float)lo0 + 256.0f * (float)hi0) * outsc;
            y[r0 + 1] = ((float)lo1 + 256.0f * (float)hi1) * outsc;
            y[r0 + 2] = ((float)lo2 + 256.0f * (float)hi2) * outsc;
        }
        grid_barrier();   // includes __threadfence before arrival
    }

    // Final normalization. Last result is in d_v0 (k=9 wrote y=d_v0).
    {
        float ss = 0.0f;
        const float4* xv = reinterpret_cast<const float4*>(d_v0);
#pragma unroll
        for (int t = 0; t < 3; t++) {
            float4 v = __ldcg(&xv[tid + 512 * t]);
            ss = fmaf(v.x, v.x, fmaf(v.y, v.y,
                 fmaf(v.z, v.z, fmaf(v.w, v.w, ss))));
        }
#pragma unroll
        for (int o = 16; o; o >>= 1) ss += __shfl_xor_sync(0xffffffffu, ss, o);
        if (lane == 0) red[warp] = ss;
        __syncthreads();
        ss = 0.0f;
#pragma unroll
        for (int w = 0; w < 16; w++) ss += red[w];
        const float inv = 1.0f / (sqrtf(ss) + 1e-6f);
        if (tid < 48) {
            const int i = blockIdx.x * 48 + tid;
            out[i] = __ldcg(&d_v0[i]) * inv;
        }
    }
}

extern "C" void kernel_launch(void* const* d_in, const int* in_sizes, int n_in,
                              void* d_out, int out_size) {
    const float* p2 = (const float*)d_in[0];  // ipts2d (N,2) fp32
    const float* p3 = (const float*)d_in[1];  // ipts3d (N,3) fp32

    dim3 bgrid(3, NPTS / 8);                  // 8x8 tile per thread
    k_build<<<bgrid, 256>>>(p2, p3);
    k_iter<<<GRID, 512>>>((float*)d_out);     // persistent: 10 iters + final
}

// round 9
// speedup vs baseline: 1.1038x; 1.0264x over previous
#include <cuda_runtime.h>

#define NPTS 6144
#define NITERS 10
#define GRID 128          // persistent grid: 1 CTA/SM, perfectly balanced wave

// Scratch (static device globals — allocation-free per harness rules)
__device__ unsigned char d_M[(size_t)NPTS * NPTS];   // 37.7 MB u8 matrix
__device__ unsigned d_part[3][NPTS];                 // per-column-block rowsums
__device__ float d_v0[NPTS];
__device__ float d_v1[NPTS];
__device__ unsigned g_cnt;   // monotone grid-barrier ticket (survives replays)

__device__ __forceinline__ float fsqrt_approx(float x) {
    float r;
    asm("sqrt.approx.f32 %0, %1;" : "=f"(r) : "f"(x));
    return r;
}

// ---- packed f32x2 helpers (sm_103a) ----
typedef unsigned long long u64t;
__device__ __forceinline__ u64t pk2(float lo, float hi) {
    u64t r; asm("mov.b64 %0, {%1, %2};" : "=l"(r) : "f"(lo), "f"(hi)); return r;
}
__device__ __forceinline__ void upk2(float& lo, float& hi, u64t v) {
    asm("mov.b64 {%0, %1}, %2;" : "=f"(lo), "=f"(hi) : "l"(v));
}
__device__ __forceinline__ u64t add2(u64t a, u64t b) {
    u64t r; asm("add.rn.f32x2 %0, %1, %2;" : "=l"(r) : "l"(a), "l"(b)); return r;
}
__device__ __forceinline__ u64t mul2(u64t a, u64t b) {
    u64t r; asm("mul.rn.f32x2 %0, %1, %2;" : "=l"(r) : "l"(a), "l"(b)); return r;
}
__device__ __forceinline__ u64t fma2(u64t a, u64t b, u64t c) {
    u64t r; asm("fma.rn.f32x2 %0, %1, %2, %3;" : "=l"(r) : "l"(a), "l"(b), "l"(c));
    return r;
}

// Build M in u8 fixed-point: q = round(255 * max(0, 1 - 100*cross^2)),
// cross^2 = a + b - 2*sqrt(a*b). Packed 2-wide via fma.rn.f32x2; 2^23
// magic-add rounding. Also computes integer rowsums (= first power
// iteration against x = ones, exactly) into d_part[bx][row] — no atomics,
// each column-block writes its own partial.
__global__ void __launch_bounds__(256) k_build(const float* __restrict__ p2,
                                               const float* __restrict__ p3) {
    const int tid = threadIdx.x;
    const int j0 = (blockIdx.x * 256 + tid) * 8;   // 8 cols
    const int r0 = blockIdx.y * 8;                 // 8 rows

    const float4* p2v = reinterpret_cast<const float4*>(p2);
    const float4* p3v = reinterpret_cast<const float4*>(p3);

    u64t ncx[4], ncy[4], n3x[4], n3y[4], n3z[4];
#pragma unroll
    for (int k = 0; k < 4; k++) {
        float4 a = __ldg(&p2v[j0 / 2 + k]);
        ncx[k] = pk2(-a.x, -a.z);
        ncy[k] = pk2(-a.y, -a.w);
    }
    {
        float q3[24];
#pragma unroll
        for (int k = 0; k < 6; k++) {
            float4 a = __ldg(&p3v[(3 * j0) / 4 + k]);
            q3[4*k] = a.x; q3[4*k+1] = a.y; q3[4*k+2] = a.z; q3[4*k+3] = a.w;
        }
#pragma unroll
        for (int k = 0; k < 4; k++) {
            n3x[k] = pk2(-q3[6*k],   -q3[6*k+3]);
            n3y[k] = pk2(-q3[6*k+1], -q3[6*k+4]);
            n3z[k] = pk2(-q3[6*k+2], -q3[6*k+5]);
        }
    }
    float rx[8], ry[8];
#pragma unroll
    for (int k = 0; k < 4; k++) {
        float4 a = __ldg(&p2v[r0 / 2 + k]);
        rx[2*k] = a.x; ry[2*k] = a.y; rx[2*k+1] = a.z; ry[2*k+1] = a.w;
    }
    float r3[24];
#pragma unroll
    for (int k = 0; k < 6; k++) {
        float4 a = __ldg(&p3v[(3 * r0) / 4 + k]);
        r3[4*k] = a.x; r3[4*k+1] = a.y; r3[4*k+2] = a.z; r3[4*k+3] = a.w;
    }

    const u64t NEG2  = pk2(-2.0f, -2.0f);
    const u64t NEGK  = pk2(-25500.0f, -25500.0f);
    const u64t MAGIC = pk2(8388863.0f, 8388863.0f);

    unsigned rs[8];
#pragma unroll
    for (int r = 0; r < 8; r++) {
        const u64t sx2 = pk2(rx[r], rx[r]);
        const u64t sy2 = pk2(ry[r], ry[r]);
        const u64t sx3 = pk2(r3[3*r],   r3[3*r]);
        const u64t sy3 = pk2(r3[3*r+1], r3[3*r+1]);
        const u64t sz3 = pk2(r3[3*r+2], r3[3*r+2]);
        unsigned u[8];
#pragma unroll
        for (int p = 0; p < 4; p++) {
            u64t dx = add2(sx2, ncx[p]);
            u64t dy = add2(sy2, ncy[p]);
            u64t a  = fma2(dx, dx, mul2(dy, dy));
            u64t d0 = add2(sx3, n3x[p]);
            u64t d1 = add2(sy3, n3y[p]);
            u64t d2 = add2(sz3, n3z[p]);
            u64t b  = fma2(d2, d2, fma2(d1, d1, mul2(d0, d0)));
            u64t ab = mul2(a, b);
            u64t apb = add2(a, b);
            float ab0, ab1;
            upk2(ab0, ab1, ab);
            u64t s  = pk2(fsqrt_approx(ab0), fsqrt_approx(ab1));
            u64t cr = fma2(NEG2, s, apb);       // (sqrt a - sqrt b)^2
            u64t t  = fma2(NEGK, cr, MAGIC);    // 2^23 + 255 - 25500*cr
            float t0, t1;
            upk2(t0, t1, t);
            t0 = fminf(fmaxf(t0, 8388608.0f), 8388863.0f);
            t1 = fminf(fmaxf(t1, 8388608.0f), 8388863.0f);
            u[2*p]   = __float_as_uint(t0);     // byte = low 8 mantissa bits
            u[2*p+1] = __float_as_uint(t1);
        }
        unsigned w0 = __byte_perm(__byte_perm(u[0], u[1], 0x0040),
                                  __byte_perm(u[2], u[3], 0x0040), 0x5410);
        unsigned w1 = __byte_perm(__byte_perm(u[4], u[5], 0x0040),
                                  __byte_perm(u[6], u[7], 0x0040), 0x5410);
        *reinterpret_cast<uint2*>(&d_M[(size_t)(r0 + r) * NPTS + j0]) =
            make_uint2(w0, w1);
        rs[r] = __dp4a(w0, 0x01010101u, __dp4a(w1, 0x01010101u, 0u));
    }

    // Block-reduce rowsum partials (exact u32) -> d_part[bx][r0..r0+8)
    __shared__ unsigned srs[8][8];   // [warp][row]
    const int lane = tid & 31, warp = tid >> 5;
#pragma unroll
    for (int r = 0; r < 8; r++) {
        unsigned v = rs[r];
#pragma unroll
        for (int o = 16; o; o >>= 1) v += __shfl_xor_sync(0xffffffffu, v, o);
        if (lane == 0) srs[warp][r] = v;
    }
    __syncthreads();
    if (tid < 8) {
        unsigned s = 0;
#pragma unroll
        for (int w = 0; w < 8; w++) s += srs[w][tid];
        d_part[blockIdx.x][r0 + tid] = s;
    }
}

// Software grid barrier. Monotone ticket counter: works across graph replays
// without reset (counter is always a multiple of GRID at barrier boundaries).
__device__ __forceinline__ void grid_barrier() {
    __syncthreads();
    if (threadIdx.x == 0) {
        __threadfence();
        unsigned old = atomicAdd(&g_cnt, 1u);
        unsigned target = old - (old % GRID) + GRID;
        while (*((volatile unsigned*)&g_cnt) < target) __nanosleep(32);
    }
    __syncthreads();
}

// Persistent kernel: iterations 1..9 + final normalization. Iteration 0
// (x = ones) was folded into k_build as exact integer rowsums; iteration 1
// reconstructs v1 = rowsum/255 from the 3 column-block partials (exact:
// sums < 2^24). grid=128, block=768: 24 warps x 2 rows = 48 rows/CTA, one
// CTA per SM so the CTA's M rows stay hot in L1 (__ldg); v/y vectors must
// bypass stale L1 (__ldcg).
__global__ void __launch_bounds__(768) k_iter(float* __restrict__ out) {
    __shared__ unsigned sxlo[NPTS / 4];   // lo bytes of xq (u16 planes)
    __shared__ unsigned sxhi[NPTS / 4];
    __shared__ float red[24];

    const int tid = threadIdx.x;
    const int warp = tid >> 5, lane = tid & 31;
    const int r0 = blockIdx.x * 48 + warp * 2;
    const uint4* M4  = reinterpret_cast<const uint4*>(d_M);
    const uint4* sl4 = reinterpret_cast<const uint4*>(sxlo);
    const uint4* sh4 = reinterpret_cast<const uint4*>(sxhi);
    const uint4* pp0 = reinterpret_cast<const uint4*>(d_part[0]);
    const uint4* pp1 = reinterpret_cast<const uint4*>(d_part[1]);
    const uint4* pp2 = reinterpret_cast<const uint4*>(d_part[2]);
    const size_t rb = (size_t)r0 * (NPTS / 16);

    for (int k = 1; k < NITERS; k++) {
        float* __restrict__ y = (k & 1) ? d_v0 : d_v1;

        // Stage x: k==1 from integer rowsum partials (exact v1 = rowsum/255),
        // else from the previous iteration's output (L2 only — L1 stale).
        float4 v[2];
        float ss = 0.0f;
        if (k == 1) {
#pragma unroll
            for (int t = 0; t < 2; t++) {
                const int f = tid + 768 * t;
                uint4 a = __ldg(&pp0[f]);
                uint4 b = __ldg(&pp1[f]);
                uint4 c = __ldg(&pp2[f]);
                v[t] = make_float4((float)(a.x + b.x + c.x) * (1.0f / 255.0f),
                                   (float)(a.y + b.y + c.y) * (1.0f / 255.0f),
                                   (float)(a.z + b.z + c.z) * (1.0f / 255.0f),
                                   (float)(a.w + b.w + c.w) * (1.0f / 255.0f));
                ss = fmaf(v[t].x, v[t].x, fmaf(v[t].y, v[t].y,
                     fmaf(v[t].z, v[t].z, fmaf(v[t].w, v[t].w, ss))));
            }
        } else {
            const float4* xv = reinterpret_cast<const float4*>(
                (k & 1) ? d_v1 : d_v0);
#pragma unroll
            for (int t = 0; t < 2; t++) {
                v[t] = __ldcg(&xv[tid + 768 * t]);
                ss = fmaf(v[t].x, v[t].x, fmaf(v[t].y, v[t].y,
                     fmaf(v[t].z, v[t].z, fmaf(v[t].w, v[t].w, ss))));
            }
        }
#pragma unroll
        for (int o = 16; o; o >>= 1) ss += __shfl_xor_sync(0xffffffffu, ss, o);
        if (lane == 0) red[warp] = ss;
        __syncthreads();
        ss = 0.0f;
#pragma unroll
        for (int w = 0; w < 24; w++) ss += red[w];

        const float inv = 1.0f / (sqrtf(ss) + 1e-6f);
        const float qs  = 65535.0f * inv;

#pragma unroll
        for (int t = 0; t < 2; t++) {
            unsigned q0 = __float2uint_rn(v[t].x * qs);
            unsigned q1 = __float2uint_rn(v[t].y * qs);
            unsigned q2 = __float2uint_rn(v[t].z * qs);
            unsigned q3 = __float2uint_rn(v[t].w * qs);
            const int f = tid + 768 * t;
            sxlo[f] = (q0 & 255u) | ((q1 & 255u) << 8) |
                      ((q2 & 255u) << 16) | ((q3 & 255u) << 24);
            sxhi[f] = (q0 >> 8) | ((q1 >> 8) << 8) |
                      ((q2 >> 8) << 16) | ((q3 >> 8) << 24);
        }
        __syncthreads();

        unsigned lo0 = 0, hi0 = 0, lo1 = 0, hi1 = 0;
#pragma unroll
        for (int it = 0; it < 12; it++) {
            const int c = it * 32 + lane;     // 16-column chunk id
            uint4 xl = sl4[c];
            uint4 xh = sh4[c];
            uint4 m0 = __ldg(&M4[rb + c]);                 // L1-cached
            uint4 m1 = __ldg(&M4[rb + (NPTS / 16) + c]);
            lo0 = __dp4a(m0.x, xl.x, lo0); hi0 = __dp4a(m0.x, xh.x, hi0);
            lo0 = __dp4a(m0.y, xl.y, lo0); hi0 = __dp4a(m0.y, xh.y, hi0);
            lo0 = __dp4a(m0.z, xl.z, lo0); hi0 = __dp4a(m0.z, xh.z, hi0);
            lo0 = __dp4a(m0.w, xl.w, lo0); hi0 = __dp4a(m0.w, xh.w, hi0);
            lo1 = __dp4a(m1.x, xl.x, lo1); hi1 = __dp4a(m1.x, xh.x, hi1);
            lo1 = __dp4a(m1.y, xl.y, lo1); hi1 = __dp4a(m1.y, xh.y, hi1);
            lo1 = __dp4a(m1.z, xl.z, lo1); hi1 = __dp4a(m1.z, xh.z, hi1);
            lo1 = __dp4a(m1.w, xl.w, lo1); hi1 = __dp4a(m1.w, xh.w, hi1);
        }
#pragma unroll
        for (int o = 16; o; o >>= 1) {
            lo0 += __shfl_xor_sync(0xffffffffu, lo0, o);
            hi0 += __shfl_xor_sync(0xffffffffu, hi0, o);
            lo1 += __shfl_xor_sync(0xffffffffu, lo1, o);
            hi1 += __shfl_xor_sync(0xffffffffu, hi1, o);
        }
        if (lane == 0) {
            const float outsc = 1.0f / (255.0f * 65535.0f);
            y[r0    ] = ((float)lo0 + 256.0f * (float)hi0) * outsc;
            y[r0 + 1] = ((float)lo1 + 256.0f * (float)hi1) * outsc;
        }
        grid_barrier();   // includes __threadfence before arrival
    }

    // Final normalization. Last result is in d_v0 (k=9 wrote y=d_v0).
    {
        float ss = 0.0f;
        const float4* xv = reinterpret_cast<const float4*>(d_v0);
#pragma unroll
        for (int t = 0; t < 2; t++) {
            float4 v = __ldcg(&xv[tid + 768 * t]);
            ss = fmaf(v.x, v.x, fmaf(v.y, v.y,
                 fmaf(v.z, v.z, fmaf(v.w, v.w, ss))));
        }
#pragma unroll
        for (int o = 16; o; o >>= 1) ss += __shfl_xor_sync(0xffffffffu, ss, o);
        if (lane == 0) red[warp] = ss;
        __syncthreads();
        ss = 0.0f;
#pragma unroll
        for (int w = 0; w < 24; w++) ss += red[w];
        const float inv = 1.0f / (sqrtf(ss) + 1e-6f);
        if (tid < 48) {
            const int i = blockIdx.x * 48 + tid;
            out[i] = __ldcg(&d_v0[i]) * inv;
        }
    }
}

extern "C" void kernel_launch(void* const* d_in, const int* in_sizes, int n_in,
                              void* d_out, int out_size) {
    const float* p2 = (const float*)d_in[0];  // ipts2d (N,2) fp32
    const float* p3 = (const float*)d_in[1];  // ipts3d (N,3) fp32

    dim3 bgrid(3, NPTS / 8);                  // 8x8 tile per thread
    k_build<<<bgrid, 256>>>(p2, p3);
    k_iter<<<GRID, 768>>>((float*)d_out);     // persistent: iters 1-9 + final
}

// round 10
// speedup vs baseline: 1.1564x; 1.0477x over previous
#include <cuda_runtime.h>

#define NPTS 6144
#define NITERS 10
#define GRID 128          // persistent grid: 1 CTA/SM, perfectly balanced wave

// Scratch (static device globals — allocation-free per harness rules)
__device__ unsigned char d_M[(size_t)NPTS * NPTS];   // 37.7 MB u8 matrix
__device__ unsigned d_part[3][NPTS];                 // per-column-block rowsums
__device__ float d_v0[NPTS];
__device__ float d_v1[NPTS];
__device__ unsigned g_cnt;   // monotone grid-barrier ticket (survives replays)

__device__ __forceinline__ float fsqrt_approx(float x) {
    float r;
    asm("sqrt.approx.f32 %0, %1;" : "=f"(r) : "f"(x));
    return r;
}

// ---- packed f32x2 helpers (sm_103a) ----
typedef unsigned long long u64t;
__device__ __forceinline__ u64t pk2(float lo, float hi) {
    u64t r; asm("mov.b64 %0, {%1, %2};" : "=l"(r) : "f"(lo), "f"(hi)); return r;
}
__device__ __forceinline__ void upk2(float& lo, float& hi, u64t v) {
    asm("mov.b64 {%0, %1}, %2;" : "=f"(lo), "=f"(hi) : "l"(v));
}
__device__ __forceinline__ u64t add2(u64t a, u64t b) {
    u64t r; asm("add.rn.f32x2 %0, %1, %2;" : "=l"(r) : "l"(a), "l"(b)); return r;
}
__device__ __forceinline__ u64t mul2(u64t a, u64t b) {
    u64t r; asm("mul.rn.f32x2 %0, %1, %2;" : "=l"(r) : "l"(a), "l"(b)); return r;
}
__device__ __forceinline__ u64t fma2(u64t a, u64t b, u64t c) {
    u64t r; asm("fma.rn.f32x2 %0, %1, %2, %3;" : "=l"(r) : "l"(a), "l"(b), "l"(c));
    return r;
}

// Build M in u8 fixed-point: q = round(255 * max(0, 1 - 100*cross^2)),
// cross^2 = a + b - 2*sqrt(a*b). Packed 2-wide via fma.rn.f32x2; 2^23
// magic-add rounding. Also computes integer rowsums (= iteration 0 against
// x = ones, exactly) into d_part[bx][row] — no atomics.
__global__ void __launch_bounds__(256) k_build(const float* __restrict__ p2,
                                               const float* __restrict__ p3) {
    const int tid = threadIdx.x;
    const int j0 = (blockIdx.x * 256 + tid) * 8;   // 8 cols
    const int r0 = blockIdx.y * 8;                 // 8 rows

    const float4* p2v = reinterpret_cast<const float4*>(p2);
    const float4* p3v = reinterpret_cast<const float4*>(p3);

    u64t ncx[4], ncy[4], n3x[4], n3y[4], n3z[4];
#pragma unroll
    for (int k = 0; k < 4; k++) {
        float4 a = __ldg(&p2v[j0 / 2 + k]);
        ncx[k] = pk2(-a.x, -a.z);
        ncy[k] = pk2(-a.y, -a.w);
    }
    {
        float q3[24];
#pragma unroll
        for (int k = 0; k < 6; k++) {
            float4 a = __ldg(&p3v[(3 * j0) / 4 + k]);
            q3[4*k] = a.x; q3[4*k+1] = a.y; q3[4*k+2] = a.z; q3[4*k+3] = a.w;
        }
#pragma unroll
        for (int k = 0; k < 4; k++) {
            n3x[k] = pk2(-q3[6*k],   -q3[6*k+3]);
            n3y[k] = pk2(-q3[6*k+1], -q3[6*k+4]);
            n3z[k] = pk2(-q3[6*k+2], -q3[6*k+5]);
        }
    }
    float rx[8], ry[8];
#pragma unroll
    for (int k = 0; k < 4; k++) {
        float4 a = __ldg(&p2v[r0 / 2 + k]);
        rx[2*k] = a.x; ry[2*k] = a.y; rx[2*k+1] = a.z; ry[2*k+1] = a.w;
    }
    float r3[24];
#pragma unroll
    for (int k = 0; k < 6; k++) {
        float4 a = __ldg(&p3v[(3 * r0) / 4 + k]);
        r3[4*k] = a.x; r3[4*k+1] = a.y; r3[4*k+2] = a.z; r3[4*k+3] = a.w;
    }

    const u64t NEG2  = pk2(-2.0f, -2.0f);
    const u64t NEGK  = pk2(-25500.0f, -25500.0f);
    const u64t MAGIC = pk2(8388863.0f, 8388863.0f);

    unsigned rs[8];
#pragma unroll
    for (int r = 0; r < 8; r++) {
        const u64t sx2 = pk2(rx[r], rx[r]);
        const u64t sy2 = pk2(ry[r], ry[r]);
        const u64t sx3 = pk2(r3[3*r],   r3[3*r]);
        const u64t sy3 = pk2(r3[3*r+1], r3[3*r+1]);
        const u64t sz3 = pk2(r3[3*r+2], r3[3*r+2]);
        unsigned u[8];
#pragma unroll
        for (int p = 0; p < 4; p++) {
            u64t dx = add2(sx2, ncx[p]);
            u64t dy = add2(sy2, ncy[p]);
            u64t a  = fma2(dx, dx, mul2(dy, dy));
            u64t d0 = add2(sx3, n3x[p]);
            u64t d1 = add2(sy3, n3y[p]);
            u64t d2 = add2(sz3, n3z[p]);
            u64t b  = fma2(d2, d2, fma2(d1, d1, mul2(d0, d0)));
            u64t ab = mul2(a, b);
            u64t apb = add2(a, b);
            float ab0, ab1;
            upk2(ab0, ab1, ab);
            u64t s  = pk2(fsqrt_approx(ab0), fsqrt_approx(ab1));
            u64t cr = fma2(NEG2, s, apb);       // (sqrt a - sqrt b)^2
            u64t t  = fma2(NEGK, cr, MAGIC);    // 2^23 + 255 - 25500*cr
            float t0, t1;
            upk2(t0, t1, t);
            t0 = fminf(fmaxf(t0, 8388608.0f), 8388863.0f);
            t1 = fminf(fmaxf(t1, 8388608.0f), 8388863.0f);
            u[2*p]   = __float_as_uint(t0);     // byte = low 8 mantissa bits
            u[2*p+1] = __float_as_uint(t1);
        }
        unsigned w0 = __byte_perm(__byte_perm(u[0], u[1], 0x0040),
                                  __byte_perm(u[2], u[3], 0x0040), 0x5410);
        unsigned w1 = __byte_perm(__byte_perm(u[4], u[5], 0x0040),
                                  __byte_perm(u[6], u[7], 0x0040), 0x5410);
        *reinterpret_cast<uint2*>(&d_M[(size_t)(r0 + r) * NPTS + j0]) =
            make_uint2(w0, w1);
        rs[r] = __dp4a(w0, 0x01010101u, __dp4a(w1, 0x01010101u, 0u));
    }

    // Block-reduce rowsum partials (exact u32) -> d_part[bx][r0..r0+8)
    __shared__ unsigned srs[8][8];   // [warp][row]
    const int lane = tid & 31, warp = tid >> 5;
#pragma unroll
    for (int r = 0; r < 8; r++) {
        unsigned v = rs[r];
#pragma unroll
        for (int o = 16; o; o >>= 1) v += __shfl_xor_sync(0xffffffffu, v, o);
        if (lane == 0) srs[warp][r] = v;
    }
    __syncthreads();
    if (tid < 8) {
        unsigned s = 0;
#pragma unroll
        for (int w = 0; w < 8; w++) s += srs[w][tid];
        d_part[blockIdx.x][r0 + tid] = s;
    }
}

// Software grid barrier. Monotone ticket counter: works across graph replays
// without reset (counter is always a multiple of GRID at barrier boundaries).
__device__ __forceinline__ void grid_barrier() {
    __syncthreads();
    if (threadIdx.x == 0) {
        __threadfence();
        unsigned old = atomicAdd(&g_cnt, 1u);
        unsigned target = old - (old % GRID) + GRID;
        while (*((volatile unsigned*)&g_cnt) < target) __nanosleep(32);
    }
    __syncthreads();
}

// Persistent kernel: iterations 1..9 + final normalization. Iteration 0 was
// folded into k_build as exact integer rowsums. x quantized to a SINGLE u8
// plane scaled by its max entry (all iterates are strictly positive):
//   xq_j = round(x_j * 255 / xmax),  y_i = (Σ q_ij xq_j) * xmax*inv/255^2
// Exact u32 accumulation (<= 6144*255^2 < 2^32). Norm (inv) still computed
// from unquantized floats, matching reference semantics.
// grid=128, block=768: 24 warps x 2 rows = 48 rows/CTA, one CTA per SM so
// M rows stay hot in L1 (__ldg); x/y vectors bypass stale L1 (__ldcg).
__global__ void __launch_bounds__(768) k_iter(float* __restrict__ out) {
    __shared__ unsigned sxq[NPTS / 4];    // u8 plane of xq
    __shared__ float red[24];
    __shared__ float redm[24];

    const int tid = threadIdx.x;
    const int warp = tid >> 5, lane = tid & 31;
    const int r0 = blockIdx.x * 48 + warp * 2;
    const uint4* M4  = reinterpret_cast<const uint4*>(d_M);
    const uint4* sq4 = reinterpret_cast<const uint4*>(sxq);
    const uint4* pp0 = reinterpret_cast<const uint4*>(d_part[0]);
    const uint4* pp1 = reinterpret_cast<const uint4*>(d_part[1]);
    const uint4* pp2 = reinterpret_cast<const uint4*>(d_part[2]);
    const size_t rb = (size_t)r0 * (NPTS / 16);

    for (int k = 1; k < NITERS; k++) {
        float* __restrict__ y = (k & 1) ? d_v0 : d_v1;

        // Stage x: k==1 from integer rowsum partials (exact v1 = rowsum/255),
        // else from the previous iteration's output (L2 only — L1 stale).
        float4 v[2];
        float ss = 0.0f, mx = 0.0f;
        if (k == 1) {
#pragma unroll
            for (int t = 0; t < 2; t++) {
                const int f = tid + 768 * t;
                uint4 a = __ldg(&pp0[f]);
                uint4 b = __ldg(&pp1[f]);
                uint4 c = __ldg(&pp2[f]);
                v[t] = make_float4((float)(a.x + b.x + c.x) * (1.0f / 255.0f),
                                   (float)(a.y + b.y + c.y) * (1.0f / 255.0f),
                                   (float)(a.z + b.z + c.z) * (1.0f / 255.0f),
                                   (float)(a.w + b.w + c.w) * (1.0f / 255.0f));
                ss = fmaf(v[t].x, v[t].x, fmaf(v[t].y, v[t].y,
                     fmaf(v[t].z, v[t].z, fmaf(v[t].w, v[t].w, ss))));
                mx = fmaxf(mx, fmaxf(fmaxf(v[t].x, v[t].y),
                                     fmaxf(v[t].z, v[t].w)));
            }
        } else {
            const float4* xv = reinterpret_cast<const float4*>(
                (k & 1) ? d_v1 : d_v0);
#pragma unroll
            for (int t = 0; t < 2; t++) {
                v[t] = __ldcg(&xv[tid + 768 * t]);
                ss = fmaf(v[t].x, v[t].x, fmaf(v[t].y, v[t].y,
                     fmaf(v[t].z, v[t].z, fmaf(v[t].w, v[t].w, ss))));
                mx = fmaxf(mx, fmaxf(fmaxf(v[t].x, v[t].y),
                                     fmaxf(v[t].z, v[t].w)));
            }
        }
#pragma unroll
        for (int o = 16; o; o >>= 1) {
            ss += __shfl_xor_sync(0xffffffffu, ss, o);
            mx = fmaxf(mx, __shfl_xor_sync(0xffffffffu, mx, o));
        }
        if (lane == 0) { red[warp] = ss; redm[warp] = mx; }
        __syncthreads();
        ss = 0.0f; mx = 0.0f;
#pragma unroll
        for (int w = 0; w < 24; w++) {
            ss += red[w];
            mx = fmaxf(mx, redm[w]);
        }

        const float inv = 1.0f / (sqrtf(ss) + 1e-6f);
        const float qs  = 255.0f / mx;                 // max-scaled u8 quant
        const float outsc = mx * inv * (1.0f / 65025.0f);

#pragma unroll
        for (int t = 0; t < 2; t++) {
            unsigned q0 = __float2uint_rn(v[t].x * qs);
            unsigned q1 = __float2uint_rn(v[t].y * qs);
            unsigned q2 = __float2uint_rn(v[t].z * qs);
            unsigned q3 = __float2uint_rn(v[t].w * qs);
            sxq[tid + 768 * t] = q0 | (q1 << 8) | (q2 << 16) | (q3 << 24);
        }
        __syncthreads();

        unsigned a0 = 0, a1 = 0;
#pragma unroll
        for (int it = 0; it < 12; it++) {
            const int c = it * 32 + lane;     // 16-column chunk id
            uint4 xq = sq4[c];
            uint4 m0 = __ldg(&M4[rb + c]);                 // L1-cached
            uint4 m1 = __ldg(&M4[rb + (NPTS / 16) + c]);
            a0 = __dp4a(m0.x, xq.x, a0);
            a0 = __dp4a(m0.y, xq.y, a0);
            a0 = __dp4a(m0.z, xq.z, a0);
            a0 = __dp4a(m0.w, xq.w, a0);
            a1 = __dp4a(m1.x, xq.x, a1);
            a1 = __dp4a(m1.y, xq.y, a1);
            a1 = __dp4a(m1.z, xq.z, a1);
            a1 = __dp4a(m1.w, xq.w, a1);
        }
#pragma unroll
        for (int o = 16; o; o >>= 1) {
            a0 += __shfl_xor_sync(0xffffffffu, a0, o);
            a1 += __shfl_xor_sync(0xffffffffu, a1, o);
        }
        if (lane == 0) {
            y[r0    ] = (float)a0 * outsc;
            y[r0 + 1] = (float)a1 * outsc;
        }
        grid_barrier();   // includes __threadfence before arrival
    }

    // Final normalization. Last result is in d_v0 (k=9 wrote y=d_v0).
    {
        float ss = 0.0f;
        const float4* xv = reinterpret_cast<const float4*>(d_v0);
#pragma unroll
        for (int t = 0; t < 2; t++) {
            float4 v = __ldcg(&xv[tid + 768 * t]);
            ss = fmaf(v.x, v.x, fmaf(v.y, v.y,
                 fmaf(v.z, v.z, fmaf(v.w, v.w, ss))));
        }
#pragma unroll
        for (int o = 16; o; o >>= 1) ss += __shfl_xor_sync(0xffffffffu, ss, o);
        if (lane == 0) red[warp] = ss;
        __syncthreads();
        ss = 0.0f;
#pragma unroll
        for (int w = 0; w < 24; w++) ss += red[w];
        const float inv = 1.0f / (sqrtf(ss) + 1e-6f);
        if (tid < 48) {
            const int i = blockIdx.x * 48 + tid;
            out[i] = __ldcg(&d_v0[i]) * inv;
        }
    }
}

extern "C" void kernel_launch(void* const* d_in, const int* in_sizes, int n_in,
                              void* d_out, int out_size) {
    const float* p2 = (const float*)d_in[0];  // ipts2d (N,2) fp32
    const float* p3 = (const float*)d_in[1];  // ipts3d (N,3) fp32

    dim3 bgrid(3, NPTS / 8);                  // 8x8 tile per thread
    k_build<<<bgrid, 256>>>(p2, p3);
    k_iter<<<GRID, 768>>>((float*)d_out);     // persistent: iters 1-9 + final
}

// round 11
// speedup vs baseline: 1.2242x; 1.0586x over previous
#include <cuda_runtime.h>

#define NPTS 6144
#define NITERS 10
#define GRID 128          // persistent grid: 1 CTA/SM, perfectly balanced wave

// Scratch (static device globals — allocation-free per harness rules)
__device__ unsigned char d_M[(size_t)NPTS * NPTS];   // 37.7 MB u8 matrix
__device__ unsigned d_part[48][NPTS];                // per-column-tile rowsums
__device__ float d_v0[NPTS];
__device__ float d_v1[NPTS];
__device__ unsigned g_cnt;   // monotone grid-barrier ticket (survives replays)

__device__ __forceinline__ float fsqrt_approx(float x) {
    float r;
    asm("sqrt.approx.f32 %0, %1;" : "=f"(r) : "f"(x));
    return r;
}

// ---- packed f32x2 helpers (sm_103a) ----
typedef unsigned long long u64t;
__device__ __forceinline__ u64t pk2(float lo, float hi) {
    u64t r; asm("mov.b64 %0, {%1, %2};" : "=l"(r) : "f"(lo), "f"(hi)); return r;
}
__device__ __forceinline__ void upk2(float& lo, float& hi, u64t v) {
    asm("mov.b64 {%0, %1}, %2;" : "=f"(lo), "=f"(hi) : "l"(v));
}
__device__ __forceinline__ u64t add2(u64t a, u64t b) {
    u64t r; asm("add.rn.f32x2 %0, %1, %2;" : "=l"(r) : "l"(a), "l"(b)); return r;
}
__device__ __forceinline__ u64t mul2(u64t a, u64t b) {
    u64t r; asm("mul.rn.f32x2 %0, %1, %2;" : "=l"(r) : "l"(a), "l"(b)); return r;
}
__device__ __forceinline__ u64t fma2(u64t a, u64t b, u64t c) {
    u64t r; asm("fma.rn.f32x2 %0, %1, %2, %3;" : "=l"(r) : "l"(a), "l"(b), "l"(c));
    return r;
}

// Build M in u8 fixed-point, SYMMETRIC: only tiles with tj >= ti are
// computed (128x128 per block, 8x8 per thread); the mirror tile is produced
// by an in-register 8x8 byte transpose (32 PRMT) and stored too. M[i][j]
// and M[j][i] are bit-identical (negated diffs square identically), so
// this matches the full computation exactly.
// Rowsums for iteration 0 (x = ones) are accumulated per column-tile into
// d_part[48][NPTS]: row-partials from the computed tile (warp shuffles),
// col-partials from the transpose (smem reduction). Every slot is written
// exactly once — no atomics, no zeroing.
__global__ void __launch_bounds__(256) k_build(const float* __restrict__ p2,
                                               const float* __restrict__ p3) {
    const int ti = blockIdx.y;        // row tile
    const int tj = blockIdx.x;        // col tile
    if (ti > tj) return;              // symmetric: upper triangle only

    const int tid = threadIdx.x;
    const int tx = tid & 15;          // col group within tile
    const int ty = tid >> 4;          // row group within tile
    const int C0 = tj * 128;
    const int R0 = ti * 128;
    const int j0 = C0 + tx * 8;       // 8 cols
    const int rr0 = R0 + ty * 8;      // 8 rows

    const float4* p2v = reinterpret_cast<const float4*>(p2);
    const float4* p3v = reinterpret_cast<const float4*>(p3);

    u64t ncx[4], ncy[4], n3x[4], n3y[4], n3z[4];
#pragma unroll
    for (int k = 0; k < 4; k++) {
        float4 a = __ldg(&p2v[j0 / 2 + k]);
        ncx[k] = pk2(-a.x, -a.z);
        ncy[k] = pk2(-a.y, -a.w);
    }
    {
        float q3[24];
#pragma unroll
        for (int k = 0; k < 6; k++) {
            float4 a = __ldg(&p3v[(3 * j0) / 4 + k]);
            q3[4*k] = a.x; q3[4*k+1] = a.y; q3[4*k+2] = a.z; q3[4*k+3] = a.w;
        }
#pragma unroll
        for (int k = 0; k < 4; k++) {
            n3x[k] = pk2(-q3[6*k],   -q3[6*k+3]);
            n3y[k] = pk2(-q3[6*k+1], -q3[6*k+4]);
            n3z[k] = pk2(-q3[6*k+2], -q3[6*k+5]);
        }
    }
    float rx[8], ry[8];
#pragma unroll
    for (int k = 0; k < 4; k++) {
        float4 a = __ldg(&p2v[rr0 / 2 + k]);
        rx[2*k] = a.x; ry[2*k] = a.y; rx[2*k+1] = a.z; ry[2*k+1] = a.w;
    }
    float r3[24];
#pragma unroll
    for (int k = 0; k < 6; k++) {
        float4 a = __ldg(&p3v[(3 * rr0) / 4 + k]);
        r3[4*k] = a.x; r3[4*k+1] = a.y; r3[4*k+2] = a.z; r3[4*k+3] = a.w;
    }

    const u64t NEG2  = pk2(-2.0f, -2.0f);
    const u64t NEGK  = pk2(-25500.0f, -25500.0f);
    const u64t MAGIC = pk2(8388863.0f, 8388863.0f);

    unsigned tl[8], th[8], rs[8];
#pragma unroll
    for (int r = 0; r < 8; r++) {
        const u64t sx2 = pk2(rx[r], rx[r]);
        const u64t sy2 = pk2(ry[r], ry[r]);
        const u64t sx3 = pk2(r3[3*r],   r3[3*r]);
        const u64t sy3 = pk2(r3[3*r+1], r3[3*r+1]);
        const u64t sz3 = pk2(r3[3*r+2], r3[3*r+2]);
        unsigned u[8];
#pragma unroll
        for (int p = 0; p < 4; p++) {
            u64t dx = add2(sx2, ncx[p]);
            u64t dy = add2(sy2, ncy[p]);
            u64t a  = fma2(dx, dx, mul2(dy, dy));
            u64t d0 = add2(sx3, n3x[p]);
            u64t d1 = add2(sy3, n3y[p]);
            u64t d2 = add2(sz3, n3z[p]);
            u64t b  = fma2(d2, d2, fma2(d1, d1, mul2(d0, d0)));
            u64t ab = mul2(a, b);
            u64t apb = add2(a, b);
            float ab0, ab1;
            upk2(ab0, ab1, ab);
            u64t s  = pk2(fsqrt_approx(ab0), fsqrt_approx(ab1));
            u64t cr = fma2(NEG2, s, apb);       // (sqrt a - sqrt b)^2
            u64t t  = fma2(NEGK, cr, MAGIC);    // 2^23 + 255 - 25500*cr
            float t0, t1;
            upk2(t0, t1, t);
            t0 = fminf(fmaxf(t0, 8388608.0f), 8388863.0f);
            t1 = fminf(fmaxf(t1, 8388608.0f), 8388863.0f);
            u[2*p]   = __float_as_uint(t0);     // byte = low 8 mantissa bits
            u[2*p+1] = __float_as_uint(t1);
        }
        unsigned w0 = __byte_perm(__byte_perm(u[0], u[1], 0x0040),
                                  __byte_perm(u[2], u[3], 0x0040), 0x5410);
        unsigned w1 = __byte_perm(__byte_perm(u[4], u[5], 0x0040),
                                  __byte_perm(u[6], u[7], 0x0040), 0x5410);
        *reinterpret_cast<uint2*>(&d_M[(size_t)(rr0 + r) * NPTS + j0]) =
            make_uint2(w0, w1);
        tl[r] = w0; th[r] = w1;
        rs[r] = __dp4a(w0, 0x01010101u, __dp4a(w1, 0x01010101u, 0u));
    }

    // Row partials: reduce rs[] across tx (16 lanes of a half-warp).
#pragma unroll
    for (int r = 0; r < 8; r++) {
        unsigned v = rs[r];
        v += __shfl_xor_sync(0xffffffffu, v, 1);
        v += __shfl_xor_sync(0xffffffffu, v, 2);
        v += __shfl_xor_sync(0xffffffffu, v, 4);
        v += __shfl_xor_sync(0xffffffffu, v, 8);
        if (tx == 0) d_part[tj][rr0 + r] = v;
    }

    __shared__ unsigned scol[128][17];   // padded col-partial staging

    if (ti != tj) {
        // 8x8 byte transpose in registers: 4 blocks of 4x4 u32-byte
        // transpose (8 PRMT each). out row c = bytes M[0..7][c].
        unsigned ol[8], oh[8];
#pragma unroll
        for (int half = 0; half < 2; half++) {          // out cols 0-3 / 4-7
            const unsigned* in = half ? th : tl;
            unsigned* o03 = half ? (ol + 4) : ol;       // C: th[0..3]->ol[4..7]
            unsigned* o47 = half ? (oh + 4) : oh;
            unsigned p0 = __byte_perm(in[0], in[1], 0x5140);
            unsigned p1 = __byte_perm(in[0], in[1], 0x7362);
            unsigned q0 = __byte_perm(in[2], in[3], 0x5140);
            unsigned q1 = __byte_perm(in[2], in[3], 0x7362);
            o03[0] = __byte_perm(p0, q0, 0x5410);
            o03[1] = __byte_perm(p0, q0, 0x7632);
            o03[2] = __byte_perm(p1, q1, 0x5410);
            o03[3] = __byte_perm(p1, q1, 0x7632);
            unsigned s0 = __byte_perm(in[4], in[5], 0x5140);
            unsigned s1 = __byte_perm(in[4], in[5], 0x7362);
            unsigned t0 = __byte_perm(in[6], in[7], 0x5140);
            unsigned t1 = __byte_perm(in[6], in[7], 0x7362);
            o47[0] = __byte_perm(s0, t0, 0x5410);
            o47[1] = __byte_perm(s0, t0, 0x7632);
            o47[2] = __byte_perm(s1, t1, 0x5410);
            o47[3] = __byte_perm(s1, t1, 0x7632);
        }
        // Store mirror tile + per-thread column sums.
#pragma unroll
        for (int c = 0; c < 8; c++) {
            *reinterpret_cast<uint2*>(
                &d_M[(size_t)(j0 + c) * NPTS + rr0]) = make_uint2(ol[c], oh[c]);
            scol[tx * 8 + c][ty] =
                __dp4a(ol[c], 0x01010101u, __dp4a(oh[c], 0x01010101u, 0u));
        }
        __syncthreads();
        if (tid < 128) {
            unsigned s = 0;
#pragma unroll
            for (int t = 0; t < 16; t++) s += scol[tid][t];
            d_part[ti][C0 + tid] = s;   // col partials = mirror-tile rows
        }
    }
}

// Software grid barrier. Monotone ticket counter: works across graph replays
// without reset (counter is always a multiple of GRID at barrier boundaries).
__device__ __forceinline__ void grid_barrier() {
    __syncthreads();
    if (threadIdx.x == 0) {
        __threadfence();
        unsigned old = atomicAdd(&g_cnt, 1u);
        unsigned target = old - (old % GRID) + GRID;
        while (*((volatile unsigned*)&g_cnt) < target) __nanosleep(32);
    }
    __syncthreads();
}

// Persistent kernel: iterations 1..9 + final normalization. Iteration 0
// (x = ones) lives in d_part as 48 exact integer partials per row; the
// prologue reduces this CTA's 48 rows into d_v1 = rowsum/255 (exact:
// sums < 2^24), then one grid barrier publishes the full vector.
// x quantized to a single u8 plane scaled by its max entry; exact u32
// dp4a accumulation; norm from unquantized floats (reference semantics).
// grid=128, block=768: 24 warps x 2 rows = 48 rows/CTA, one CTA per SM so
// M rows stay hot in L1 (__ldg); x/y vectors bypass stale L1 (__ldcg).
__global__ void __launch_bounds__(768) k_iter(float* __restrict__ out) {
    __shared__ unsigned sxq[NPTS / 4];    // u8 plane of xq
    __shared__ float red[24];
    __shared__ float redm[24];

    const int tid = threadIdx.x;
    const int warp = tid >> 5, lane = tid & 31;
    const int r0 = blockIdx.x * 48 + warp * 2;
    const uint4* M4  = reinterpret_cast<const uint4*>(d_M);
    const uint4* sq4 = reinterpret_cast<const uint4*>(sxq);
    const size_t rb = (size_t)r0 * (NPTS / 16);

    // Prologue: v1[row] = (sum of 48 column-tile partials)/255 for this
    // CTA's own 48 rows. 8 threads per row, shuffle-reduced.
    if (tid < 384) {
        const int rloc = tid >> 3;
        const int seg  = tid & 7;
        const int row  = blockIdx.x * 48 + rloc;
        unsigned s = 0;
#pragma unroll
        for (int a = 0; a < 6; a++)
            s += d_part[seg * 6 + a][row];
        s += __shfl_xor_sync(0xffffffffu, s, 1);
        s += __shfl_xor_sync(0xffffffffu, s, 2);
        s += __shfl_xor_sync(0xffffffffu, s, 4);
        if (seg == 0) d_v1[row] = (float)s * (1.0f / 255.0f);
    }
    grid_barrier();

    for (int k = 1; k < NITERS; k++) {
        float* __restrict__ y = (k & 1) ? d_v0 : d_v1;
        const float4* xv = reinterpret_cast<const float4*>(
            (k & 1) ? d_v1 : d_v0);

        // Stage x (L2 only — L1 may hold stale lines), norm + max.
        float4 v[2];
        float ss = 0.0f, mx = 0.0f;
#pragma unroll
        for (int t = 0; t < 2; t++) {
            v[t] = __ldcg(&xv[tid + 768 * t]);
            ss = fmaf(v[t].x, v[t].x, fmaf(v[t].y, v[t].y,
                 fmaf(v[t].z, v[t].z, fmaf(v[t].w, v[t].w, ss))));
            mx = fmaxf(mx, fmaxf(fmaxf(v[t].x, v[t].y),
                                 fmaxf(v[t].z, v[t].w)));
        }
#pragma unroll
        for (int o = 16; o; o >>= 1) {
            ss += __shfl_xor_sync(0xffffffffu, ss, o);
            mx = fmaxf(mx, __shfl_xor_sync(0xffffffffu, mx, o));
        }
        if (lane == 0) { red[warp] = ss; redm[warp] = mx; }
        __syncthreads();
        ss = 0.0f; mx = 0.0f;
#pragma unroll
        for (int w = 0; w < 24; w++) {
            ss += red[w];
            mx = fmaxf(mx, redm[w]);
        }

        const float inv = 1.0f / (sqrtf(ss) + 1e-6f);
        const float qs  = 255.0f / mx;                 // max-scaled u8 quant
        const float outsc = mx * inv * (1.0f / 65025.0f);

#pragma unroll
        for (int t = 0; t < 2; t++) {
            unsigned q0 = __float2uint_rn(v[t].x * qs);
            unsigned q1 = __float2uint_rn(v[t].y * qs);
            unsigned q2 = __float2uint_rn(v[t].z * qs);
            unsigned q3 = __float2uint_rn(v[t].w * qs);
            sxq[tid + 768 * t] = q0 | (q1 << 8) | (q2 << 16) | (q3 << 24);
        }
        __syncthreads();

        unsigned a0 = 0, a1 = 0;
#pragma unroll
        for (int it = 0; it < 12; it++) {
            const int c = it * 32 + lane;     // 16-column chunk id
            uint4 xq = sq4[c];
            uint4 m0 = __ldg(&M4[rb + c]);                 // L1-cached
            uint4 m1 = __ldg(&M4[rb + (NPTS / 16) + c]);
            a0 = __dp4a(m0.x, xq.x, a0);
            a0 = __dp4a(m0.y, xq.y, a0);
            a0 = __dp4a(m0.z, xq.z, a0);
            a0 = __dp4a(m0.w, xq.w, a0);
            a1 = __dp4a(m1.x, xq.x, a1);
            a1 = __dp4a(m1.y, xq.y, a1);
            a1 = __dp4a(m1.z, xq.z, a1);
            a1 = __dp4a(m1.w, xq.w, a1);
        }
#pragma unroll
        for (int o = 16; o; o >>= 1) {
            a0 += __shfl_xor_sync(0xffffffffu, a0, o);
            a1 += __shfl_xor_sync(0xffffffffu, a1, o);
        }
        if (lane == 0) {
            y[r0    ] = (float)a0 * outsc;
            y[r0 + 1] = (float)a1 * outsc;
        }
        grid_barrier();   // includes __threadfence before arrival
    }

    // Final normalization. Last result is in d_v0 (k=9 wrote y=d_v0).
    {
        float ss = 0.0f;
        const float4* xv = reinterpret_cast<const float4*>(d_v0);
#pragma unroll
        for (int t = 0; t < 2; t++) {
            float4 v = __ldcg(&xv[tid + 768 * t]);
            ss = fmaf(v.x, v.x, fmaf(v.y, v.y,
                 fmaf(v.z, v.z, fmaf(v.w, v.w, ss))));
        }
#pragma unroll
        for (int o = 16; o; o >>= 1) ss += __shfl_xor_sync(0xffffffffu, ss, o);
        if (lane == 0) red[warp] = ss;
        __syncthreads();
        ss = 0.0f;
#pragma unroll
        for (int w = 0; w < 24; w++) ss += red[w];
        const float inv = 1.0f / (sqrtf(ss) + 1e-6f);
        if (tid < 48) {
            const int i = blockIdx.x * 48 + tid;
            out[i] = __ldcg(&d_v0[i]) * inv;
        }
    }
}

extern "C" void kernel_launch(void* const* d_in, const int* in_sizes, int n_in,
                              void* d_out, int out_size) {
    const float* p2 = (const float*)d_in[0];  // ipts2d (N,2) fp32
    const float* p3 = (const float*)d_in[1];  // ipts3d (N,3) fp32

    dim3 bgrid(48, 48);                       // 128x128 tiles; ti<=tj compute
    k_build<<<bgrid, 256>>>(p2, p3);
    k_iter<<<GRID, 768>>>((float*)d_out);     // persistent: iters 1-9 + final
}